// round 4
// baseline (speedup 1.0000x reference)
#include <cuda_runtime.h>
#include <stdint.h>

#define NN 100000
#define FIN 128
#define HID 32
#define G3 96
#define NE 3200000

// ---- device scratch ----
__device__ float g_dinv[NN];
__device__ float g_deg[NN];
__device__ int   g_cnt[NN];
__device__ int   g_rowstart[NN];
__device__ int   g_cursor[NN];
__device__ int   g_bsum[128];
__device__ unsigned long long g_edges[NE];     // packed (row:int32, raw w:f32)
__device__ float g_U[(size_t)NN * G3];         // dinv[n] * (x @ Vc)  (pre-scaled)
__device__ float g_Vc[FIN * G3];
__device__ float g_cst[G3];
__device__ float g_Wt[3 * HID * HID];
__device__ int   g_is64;

__device__ __forceinline__ int edge_idx(const void* ei, size_t pos) {
    if (g_is64) return (int)__ldg(((const long long*)ei) + pos);
    return __ldg(((const int*)ei) + pos);
}

__device__ __forceinline__ void ffma2(unsigned long long& d,
                                      unsigned long long a,
                                      unsigned long long b) {
    asm("fma.rn.f32x2 %0, %1, %2, %0;" : "+l"(d) : "l"(a), "l"(b));
}
__device__ __forceinline__ unsigned long long packff(float x, float y) {
    unsigned long long r;
    asm("mov.b64 %0, {%1, %2};" : "=l"(r) : "f"(x), "f"(y));
    return r;
}

// ---------------------------------------------------------------------------
__global__ void detect_kernel(const int* __restrict__ ei_words) {
    __shared__ int nz;
    if (threadIdx.x == 0) nz = 0;
    __syncthreads();
    for (int i = threadIdx.x; i < 4096; i += blockDim.x)
        if ((i & 1) && ei_words[i] != 0) atomicOr(&nz, 1);
    __syncthreads();
    if (threadIdx.x == 0) g_is64 = (nz == 0) ? 1 : 0;
}

// ---------------------------------------------------------------------------
__global__ void prep_kernel(
    const float* Wc0, const float* bc0, const float* Wl0, const float* bl0,
    const float* Wc1, const float* bc1, const float* Wl1, const float* bl1,
    const float* Wc2, const float* bc2, const float* Wl2, const float* bl2)
{
    const float* Wc[3] = {Wc0, Wc1, Wc2};
    const float* bc[3] = {bc0, bc1, bc2};
    const float* Wl[3] = {Wl0, Wl1, Wl2};
    const float* bl[3] = {bl0, bl1, bl2};
    int t = threadIdx.x;            // 128 threads
    int k = t;
    for (int g = 0; g < 3; g++) {
        const float* wc_row = Wc[g] + (size_t)k * HID;
        for (int j = 0; j < HID; j++) {
            const float* wl_row = Wl[g] + (size_t)j * 2 * HID;
            float s = 0.f;
            #pragma unroll
            for (int tt = 0; tt < HID; tt++) s += wc_row[tt] * wl_row[tt];
            g_Vc[k * G3 + g * HID + j] = s;
        }
    }
    if (t < G3) {
        int g = t / HID, j = t % HID;
        const float* wl_row = Wl[g] + (size_t)j * 2 * HID;
        float s = bl[g][j];
        #pragma unroll
        for (int tt = 0; tt < HID; tt++) s += bc[g][tt] * wl_row[tt];
        g_cst[t] = s;
        for (int k2 = 0; k2 < HID; k2++)
            g_Wt[g * HID * HID + k2 * HID + j] = wl_row[HID + k2];
    }
}

// ---------------------------------------------------------------------------
__global__ void init_kernel() {
    int i = blockIdx.x * blockDim.x + threadIdx.x;
    if (i < NN) { g_deg[i] = 1.0f; g_cnt[i] = 0; }
}

__global__ void count_kernel(const void* __restrict__ ei,
                             const float* __restrict__ ew) {
    int e = blockIdx.x * blockDim.x + threadIdx.x;
    if (e < NE) {
        int c = edge_idx(ei, (size_t)NE + e);
        atomicAdd(&g_cnt[c], 1);
        atomicAdd(&g_deg[c], __ldg(&ew[e]));
    }
}

// ---------------------------------------------------------------------------
__global__ void __launch_bounds__(1024) scanA_kernel() {
    __shared__ int wsum[32];
    int tid = threadIdx.x, lane = tid & 31, wid = tid >> 5;
    int i = blockIdx.x * 1024 + tid;
    int v = (i < NN) ? g_cnt[i] : 0;
    int s = v;
    #pragma unroll
    for (int off = 1; off < 32; off <<= 1) {
        int t = __shfl_up_sync(0xffffffffu, s, off);
        if (lane >= off) s += t;
    }
    if (lane == 31) wsum[wid] = s;
    __syncthreads();
    if (wid == 0) {
        int t = wsum[lane];
        #pragma unroll
        for (int off = 1; off < 32; off <<= 1) {
            int u = __shfl_up_sync(0xffffffffu, t, off);
            if (lane >= off) t += u;
        }
        wsum[lane] = t;
    }
    __syncthreads();
    int woff = (wid > 0) ? wsum[wid - 1] : 0;
    if (i < NN) g_rowstart[i] = s - v + woff;
    if (tid == 1023) g_bsum[blockIdx.x] = s + woff;
}

__global__ void scanB_kernel(int nblk) {
    __shared__ int tmp[128];
    int t = threadIdx.x;
    tmp[t] = (t < nblk) ? g_bsum[t] : 0;
    __syncthreads();
    if (t == 0) {
        int acc = 0;
        for (int i = 0; i < nblk; i++) { int v = tmp[i]; tmp[i] = acc; acc += v; }
    }
    __syncthreads();
    if (t < nblk) g_bsum[t] = tmp[t];
}

__global__ void __launch_bounds__(1024) scanC_kernel() {
    int i = blockIdx.x * 1024 + threadIdx.x;
    if (i < NN) {
        int rs = g_rowstart[i] + g_bsum[blockIdx.x];
        g_rowstart[i] = rs;
        g_cursor[i]   = rs;
        g_dinv[i]     = rsqrtf(g_deg[i]);
    }
}

// ---------------------------------------------------------------------------
// scatter raw (row, w) into CSR buckets (no dinv loads here)
// ---------------------------------------------------------------------------
__global__ void scatter_kernel(const void* __restrict__ ei,
                               const float* __restrict__ ew) {
    int e = blockIdx.x * blockDim.x + threadIdx.x;
    if (e >= NE) return;
    int   r = edge_idx(ei, e);
    int   c = edge_idx(ei, (size_t)NE + e);
    float w = __ldg(&ew[e]);
    int pos = atomicAdd(&g_cursor[c], 1);
    g_edges[pos] = (unsigned long long)(unsigned)r |
                   ((unsigned long long)__float_as_uint(w) << 32);
}

// ---------------------------------------------------------------------------
// U' = dinv .* (x @ Vc)   (100000x128 @ 128x96), f32x2 dual-FMA inner loop.
// 64 nodes x 96 feats per block; thread = 4 node-pairs x 3 feature groups.
// ---------------------------------------------------------------------------
__global__ void __launch_bounds__(256) gemm_u_kernel(const float* __restrict__ x) {
    __shared__ float xs[32][66];     // [kk][node] transposed, padded
    __shared__ float vs[32][96];     // [kk][feat]
    int tid = threadIdx.x;
    int rg = tid >> 5, cj = tid & 31;
    int m0 = blockIdx.x * 64;

    unsigned long long acc[4][3];
    #pragma unroll
    for (int p = 0; p < 4; p++)
        #pragma unroll
        for (int t = 0; t < 3; t++) acc[p][t] = 0ull;

    for (int kb = 0; kb < FIN; kb += 32) {
        #pragma unroll
        for (int i = 0; i < 2; i++) {
            int s = tid + i * 256;
            int nd = s >> 3, k4 = s & 7;
            int gn = m0 + nd; if (gn >= NN) gn = NN - 1;
            float4 v = *(const float4*)&x[(size_t)gn * FIN + kb + k4 * 4];
            xs[k4 * 4 + 0][nd] = v.x;
            xs[k4 * 4 + 1][nd] = v.y;
            xs[k4 * 4 + 2][nd] = v.z;
            xs[k4 * 4 + 3][nd] = v.w;
        }
        #pragma unroll
        for (int i = 0; i < 12; i++) {
            int idx = tid + i * 256;
            int kk = idx / 96, j = idx - kk * 96;
            vs[kk][j] = g_Vc[(kb + kk) * G3 + j];
        }
        __syncthreads();
        #pragma unroll
        for (int kk = 0; kk < 32; kk++) {
            unsigned long long xp[4];
            #pragma unroll
            for (int p = 0; p < 4; p++)
                xp[p] = *(const unsigned long long*)&xs[kk][rg * 8 + p * 2];
            float b0 = vs[kk][cj], b1 = vs[kk][cj + 32], b2 = vs[kk][cj + 64];
            unsigned long long bb0 = packff(b0, b0);
            unsigned long long bb1 = packff(b1, b1);
            unsigned long long bb2 = packff(b2, b2);
            #pragma unroll
            for (int p = 0; p < 4; p++) {
                ffma2(acc[p][0], xp[p], bb0);
                ffma2(acc[p][1], xp[p], bb1);
                ffma2(acc[p][2], xp[p], bb2);
            }
        }
        __syncthreads();
    }
    #pragma unroll
    for (int p = 0; p < 4; p++) {
        int n0 = m0 + rg * 8 + p * 2;
        if (n0 >= NN) continue;
        float d0 = g_dinv[n0];
        bool ok1 = (n0 + 1 < NN);
        float d1 = ok1 ? g_dinv[n0 + 1] : 0.f;
        #pragma unroll
        for (int t = 0; t < 3; t++) {
            union { unsigned long long u; float2 f; } cv; cv.u = acc[p][t];
            g_U[(size_t)n0 * G3 + cj + t * 32] = cv.f.x * d0;
            if (ok1) g_U[(size_t)(n0 + 1) * G3 + cj + t * 32] = cv.f.y * d1;
        }
    }
}

// ---------------------------------------------------------------------------
// fused gather + gates + head.
// 768 threads = 24 warps = 8 nodes x 3 feature-group warps. Then 8 gate warps.
// ---------------------------------------------------------------------------
__global__ void __launch_bounds__(768) gather_gates_kernel(
    const float* __restrict__ hprev,
    const float* __restrict__ whead,
    const float* __restrict__ bhead,
    float* __restrict__ out)
{
    __shared__ float Ws[3 * HID * HID];
    __shared__ float csts[G3];
    __shared__ float sagg[8][G3];
    int tid = threadIdx.x;
    for (int i = tid; i < 3 * HID * HID; i += 768) Ws[i] = g_Wt[i];
    if (tid < G3) csts[tid] = g_cst[tid];

    int w = tid >> 5, lane = tid & 31;
    int nd = w / 3;                        // 0..7
    int grp = w - nd * 3;                  // 0..2
    int n = blockIdx.x * 8 + nd;
    int off = grp * 32 + lane;

    const float* ub = g_U + off;
    float acc = __ldg(&g_U[(size_t)n * G3 + off]);   // self loop (w=1)

    int start = __ldg(&g_rowstart[n]);
    int cnt   = __ldg(&g_cnt[n]);
    const unsigned long long* el = g_edges + start;
    int j = 0;
    for (; j + 32 <= cnt; j += 32) {
        unsigned long long pk = __ldg(&el[j + lane]);
        #pragma unroll
        for (int t = 0; t < 32; t += 4) {
            unsigned long long p0 = __shfl_sync(0xffffffffu, pk, t);
            unsigned long long p1 = __shfl_sync(0xffffffffu, pk, t + 1);
            unsigned long long p2 = __shfl_sync(0xffffffffu, pk, t + 2);
            unsigned long long p3 = __shfl_sync(0xffffffffu, pk, t + 3);
            float v0 = __ldg(&ub[(size_t)(unsigned)p0 * G3]);
            float v1 = __ldg(&ub[(size_t)(unsigned)p1 * G3]);
            float v2 = __ldg(&ub[(size_t)(unsigned)p2 * G3]);
            float v3 = __ldg(&ub[(size_t)(unsigned)p3 * G3]);
            acc = fmaf(__uint_as_float((unsigned)(p0 >> 32)), v0, acc);
            acc = fmaf(__uint_as_float((unsigned)(p1 >> 32)), v1, acc);
            acc = fmaf(__uint_as_float((unsigned)(p2 >> 32)), v2, acc);
            acc = fmaf(__uint_as_float((unsigned)(p3 >> 32)), v3, acc);
        }
    }
    int rem = cnt - j;
    if (rem > 0) {
        unsigned long long pk = (lane < rem) ? __ldg(&el[j + lane]) : 0ull;
        for (int t = 0; t < rem; t++) {
            unsigned long long p = __shfl_sync(0xffffffffu, pk, t);
            float v = __ldg(&ub[(size_t)(unsigned)p * G3]);
            acc = fmaf(__uint_as_float((unsigned)(p >> 32)), v, acc);
        }
    }
    sagg[nd][off] = acc * __ldg(&g_dinv[n]);
    __syncthreads();

    // ---- gates: warps 0..7, one node each ----
    if (w < 8) {
        int n2 = blockIdx.x * 8 + w;
        float h  = hprev[(size_t)n2 * HID + lane];
        float zp = sagg[w][lane]      + csts[lane];
        float rp = sagg[w][lane + 32] + csts[lane + 32];
        float hp = sagg[w][lane + 64] + csts[lane + 64];

        const float* Wz = Ws;
        const float* Wr = Ws + HID * HID;
        const float* Wh = Ws + 2 * HID * HID;
        #pragma unroll
        for (int k = 0; k < HID; k++) {
            float hk = __shfl_sync(0xffffffffu, h, k);
            zp += hk * Wz[k * HID + lane];
            rp += hk * Wr[k * HID + lane];
        }
        float Z = 1.f / (1.f + __expf(-zp));
        float R = 1.f / (1.f + __expf(-rp));
        float hr = h * R;
        #pragma unroll
        for (int k = 0; k < HID; k++) {
            float hk = __shfl_sync(0xffffffffu, hr, k);
            hp += hk * Wh[k * HID + lane];
        }
        float Ht = tanhf(hp);
        float Hn = Z * h + (1.f - Z) * Ht;

        out[(size_t)NN + (size_t)n2 * HID + lane] = Hn;

        float yv = fmaxf(Hn, 0.f) * __ldg(&whead[lane]);
        #pragma unroll
        for (int o = 16; o > 0; o >>= 1)
            yv += __shfl_down_sync(0xffffffffu, yv, o);
        if (lane == 0) out[n2] = yv + __ldg(bhead);
    }
}

// ---------------------------------------------------------------------------
extern "C" void kernel_launch(void* const* d_in, const int* in_sizes, int n_in,
                              void* d_out, int out_size) {
    const float* x     = (const float*)d_in[0];
    const void*  ei    = d_in[1];
    const float* ew    = (const float*)d_in[2];
    const float* hprev = (const float*)d_in[3];
    const float* Wc[3], *bc[3], *Wl[3], *bl[3];
    for (int g = 0; g < 3; g++) {
        Wc[g] = (const float*)d_in[4 + g * 4];
        bc[g] = (const float*)d_in[5 + g * 4];
        Wl[g] = (const float*)d_in[6 + g * 4];
        bl[g] = (const float*)d_in[7 + g * 4];
    }
    const float* whead = (const float*)d_in[16];
    const float* bhead = (const float*)d_in[17];
    float* out = (float*)d_out;

    const int nscan = (NN + 1023) / 1024;   // 98

    detect_kernel<<<1, 256>>>((const int*)ei);
    prep_kernel<<<1, 128>>>(Wc[0], bc[0], Wl[0], bl[0],
                            Wc[1], bc[1], Wl[1], bl[1],
                            Wc[2], bc[2], Wl[2], bl[2]);
    init_kernel<<<(NN + 255) / 256, 256>>>();
    count_kernel<<<(NE + 255) / 256, 256>>>(ei, ew);
    scanA_kernel<<<nscan, 1024>>>();
    scanB_kernel<<<1, 128>>>(nscan);
    scanC_kernel<<<nscan, 1024>>>();
    gemm_u_kernel<<<(NN + 63) / 64, 256>>>(x);
    scatter_kernel<<<(NE + 255) / 256, 256>>>(ei, ew);
    gather_gates_kernel<<<NN / 8, 768>>>(hprev, whead, bhead, out);
}

// round 5
// speedup vs baseline: 1.2390x; 1.2390x over previous
#include <cuda_runtime.h>
#include <stdint.h>

#define NN 100000
#define FIN 128
#define HID 32
#define G3 96
#define NE 3200000

// ---- device scratch ----
__device__ float g_dinv[NN];
__device__ float g_deg[NN];
__device__ int   g_cnt[NN];
__device__ int   g_rowstart[NN];
__device__ int   g_cursor[NN];
__device__ int   g_bsum[128];
__device__ unsigned long long g_edges[NE];     // packed (row:int32, raw w:f32)
__device__ float g_U[(size_t)NN * G3];         // dinv[n] * (x @ Vc)  (pre-scaled)
__device__ float g_Vc[FIN * G3];
__device__ float g_cst[G3];
__device__ float g_Wt[3 * HID * HID];
__device__ int   g_is64;

__device__ __forceinline__ int edge_idx(const void* ei, size_t pos) {
    if (g_is64) return (int)__ldg(((const long long*)ei) + pos);
    return __ldg(((const int*)ei) + pos);
}

__device__ __forceinline__ void ffma2(unsigned long long& d,
                                      unsigned long long a,
                                      unsigned long long b) {
    asm("fma.rn.f32x2 %0, %1, %2, %0;" : "+l"(d) : "l"(a), "l"(b));
}
__device__ __forceinline__ unsigned long long packff(float x, float y) {
    unsigned long long r;
    asm("mov.b64 %0, {%1, %2};" : "=l"(r) : "f"(x), "f"(y));
    return r;
}

// ---------------------------------------------------------------------------
__global__ void detect_kernel(const int* __restrict__ ei_words) {
    __shared__ int nz;
    if (threadIdx.x == 0) nz = 0;
    __syncthreads();
    for (int i = threadIdx.x; i < 4096; i += blockDim.x)
        if ((i & 1) && ei_words[i] != 0) atomicOr(&nz, 1);
    __syncthreads();
    if (threadIdx.x == 0) g_is64 = (nz == 0) ? 1 : 0;
}

// ---------------------------------------------------------------------------
__global__ void prep_kernel(
    const float* Wc0, const float* bc0, const float* Wl0, const float* bl0,
    const float* Wc1, const float* bc1, const float* Wl1, const float* bl1,
    const float* Wc2, const float* bc2, const float* Wl2, const float* bl2)
{
    const float* Wc[3] = {Wc0, Wc1, Wc2};
    const float* bc[3] = {bc0, bc1, bc2};
    const float* Wl[3] = {Wl0, Wl1, Wl2};
    const float* bl[3] = {bl0, bl1, bl2};
    int t = threadIdx.x;            // 128 threads
    int k = t;
    for (int g = 0; g < 3; g++) {
        const float* wc_row = Wc[g] + (size_t)k * HID;
        for (int j = 0; j < HID; j++) {
            const float* wl_row = Wl[g] + (size_t)j * 2 * HID;
            float s = 0.f;
            #pragma unroll
            for (int tt = 0; tt < HID; tt++) s += wc_row[tt] * wl_row[tt];
            g_Vc[k * G3 + g * HID + j] = s;
        }
    }
    if (t < G3) {
        int g = t / HID, j = t % HID;
        const float* wl_row = Wl[g] + (size_t)j * 2 * HID;
        float s = bl[g][j];
        #pragma unroll
        for (int tt = 0; tt < HID; tt++) s += bc[g][tt] * wl_row[tt];
        g_cst[t] = s;
        for (int k2 = 0; k2 < HID; k2++)
            g_Wt[g * HID * HID + k2 * HID + j] = wl_row[HID + k2];
    }
}

// ---------------------------------------------------------------------------
__global__ void init_kernel() {
    int i = blockIdx.x * blockDim.x + threadIdx.x;
    if (i < NN) { g_deg[i] = 1.0f; g_cnt[i] = 0; }
}

__global__ void count_kernel(const void* __restrict__ ei,
                             const float* __restrict__ ew) {
    int e = blockIdx.x * blockDim.x + threadIdx.x;
    if (e < NE) {
        int c = edge_idx(ei, (size_t)NE + e);
        atomicAdd(&g_cnt[c], 1);
        atomicAdd(&g_deg[c], __ldg(&ew[e]));
    }
}

// ---------------------------------------------------------------------------
__global__ void __launch_bounds__(1024) scanA_kernel() {
    __shared__ int wsum[32];
    int tid = threadIdx.x, lane = tid & 31, wid = tid >> 5;
    int i = blockIdx.x * 1024 + tid;
    int v = (i < NN) ? g_cnt[i] : 0;
    int s = v;
    #pragma unroll
    for (int off = 1; off < 32; off <<= 1) {
        int t = __shfl_up_sync(0xffffffffu, s, off);
        if (lane >= off) s += t;
    }
    if (lane == 31) wsum[wid] = s;
    __syncthreads();
    if (wid == 0) {
        int t = wsum[lane];
        #pragma unroll
        for (int off = 1; off < 32; off <<= 1) {
            int u = __shfl_up_sync(0xffffffffu, t, off);
            if (lane >= off) t += u;
        }
        wsum[lane] = t;
    }
    __syncthreads();
    int woff = (wid > 0) ? wsum[wid - 1] : 0;
    if (i < NN) g_rowstart[i] = s - v + woff;
    if (tid == 1023) g_bsum[blockIdx.x] = s + woff;
}

__global__ void scanB_kernel(int nblk) {
    __shared__ int tmp[128];
    int t = threadIdx.x;
    tmp[t] = (t < nblk) ? g_bsum[t] : 0;
    __syncthreads();
    if (t == 0) {
        int acc = 0;
        for (int i = 0; i < nblk; i++) { int v = tmp[i]; tmp[i] = acc; acc += v; }
    }
    __syncthreads();
    if (t < nblk) g_bsum[t] = tmp[t];
}

__global__ void __launch_bounds__(1024) scanC_kernel() {
    int i = blockIdx.x * 1024 + threadIdx.x;
    if (i < NN) {
        int rs = g_rowstart[i] + g_bsum[blockIdx.x];
        g_rowstart[i] = rs;
        g_cursor[i]   = rs;
        g_dinv[i]     = rsqrtf(g_deg[i]);
    }
}

// ---------------------------------------------------------------------------
// scatter raw (row, w) into CSR buckets (no dinv loads here)
// ---------------------------------------------------------------------------
__global__ void scatter_kernel(const void* __restrict__ ei,
                               const float* __restrict__ ew) {
    int e = blockIdx.x * blockDim.x + threadIdx.x;
    if (e >= NE) return;
    int   r = edge_idx(ei, e);
    int   c = edge_idx(ei, (size_t)NE + e);
    float w = __ldg(&ew[e]);
    int pos = atomicAdd(&g_cursor[c], 1);
    g_edges[pos] = (unsigned long long)(unsigned)r |
                   ((unsigned long long)__float_as_uint(w) << 32);
}

// ---------------------------------------------------------------------------
// U' = dinv .* (x @ Vc)   (100000x128 @ 128x96), f32x2 dual-FMA inner loop.
// ---------------------------------------------------------------------------
__global__ void __launch_bounds__(256) gemm_u_kernel(const float* __restrict__ x) {
    __shared__ float xs[32][66];     // [kk][node] transposed, padded
    __shared__ float vs[32][96];     // [kk][feat]
    int tid = threadIdx.x;
    int rg = tid >> 5, cj = tid & 31;
    int m0 = blockIdx.x * 64;

    unsigned long long acc[4][3];
    #pragma unroll
    for (int p = 0; p < 4; p++)
        #pragma unroll
        for (int t = 0; t < 3; t++) acc[p][t] = 0ull;

    for (int kb = 0; kb < FIN; kb += 32) {
        #pragma unroll
        for (int i = 0; i < 2; i++) {
            int s = tid + i * 256;
            int nd = s >> 3, k4 = s & 7;
            int gn = m0 + nd; if (gn >= NN) gn = NN - 1;
            float4 v = *(const float4*)&x[(size_t)gn * FIN + kb + k4 * 4];
            xs[k4 * 4 + 0][nd] = v.x;
            xs[k4 * 4 + 1][nd] = v.y;
            xs[k4 * 4 + 2][nd] = v.z;
            xs[k4 * 4 + 3][nd] = v.w;
        }
        #pragma unroll
        for (int i = 0; i < 12; i++) {
            int idx = tid + i * 256;
            int kk = idx / 96, j = idx - kk * 96;
            vs[kk][j] = g_Vc[(kb + kk) * G3 + j];
        }
        __syncthreads();
        #pragma unroll
        for (int kk = 0; kk < 32; kk++) {
            unsigned long long xp[4];
            #pragma unroll
            for (int p = 0; p < 4; p++)
                xp[p] = *(const unsigned long long*)&xs[kk][rg * 8 + p * 2];
            float b0 = vs[kk][cj], b1 = vs[kk][cj + 32], b2 = vs[kk][cj + 64];
            unsigned long long bb0 = packff(b0, b0);
            unsigned long long bb1 = packff(b1, b1);
            unsigned long long bb2 = packff(b2, b2);
            #pragma unroll
            for (int p = 0; p < 4; p++) {
                ffma2(acc[p][0], xp[p], bb0);
                ffma2(acc[p][1], xp[p], bb1);
                ffma2(acc[p][2], xp[p], bb2);
            }
        }
        __syncthreads();
    }
    #pragma unroll
    for (int p = 0; p < 4; p++) {
        int n0 = m0 + rg * 8 + p * 2;
        if (n0 >= NN) continue;
        float d0 = g_dinv[n0];
        bool ok1 = (n0 + 1 < NN);
        float d1 = ok1 ? g_dinv[n0 + 1] : 0.f;
        #pragma unroll
        for (int t = 0; t < 3; t++) {
            union { unsigned long long u; float2 f; } cv; cv.u = acc[p][t];
            g_U[(size_t)n0 * G3 + cj + t * 32] = cv.f.x * d0;
            if (ok1) g_U[(size_t)(n0 + 1) * G3 + cj + t * 32] = cv.f.y * d1;
        }
    }
}

// ---------------------------------------------------------------------------
// fused gather + gates + head. Warp per node, lane = hidden feature.
// 4-edge unrolled inner loop: 12 independent L2 loads in flight per warp.
// ---------------------------------------------------------------------------
__global__ void __launch_bounds__(256) gather_gates_kernel(
    const float* __restrict__ hprev,
    const float* __restrict__ whead,
    const float* __restrict__ bhead,
    float* __restrict__ out)
{
    __shared__ float Ws[3 * HID * HID];
    __shared__ float csts[G3];
    int tid = threadIdx.x;
    for (int i = tid; i < 3 * HID * HID; i += 256) Ws[i] = g_Wt[i];
    if (tid < G3) csts[tid] = g_cst[tid];
    __syncthreads();

    int warp = tid >> 5, lane = tid & 31;
    int n = blockIdx.x * 8 + warp;       // grid = 12500 -> exactly N nodes

    // self-loop: U' already has dinv[n]; final scale dinv[n] applied at end
    const float* un = g_U + (size_t)n * G3;
    float a0 = __ldg(un + lane);
    float a1 = __ldg(un + lane + 32);
    float a2 = __ldg(un + lane + 64);

    int start = __ldg(&g_rowstart[n]);
    int cnt   = __ldg(&g_cnt[n]);
    const unsigned long long* el = g_edges + start;

    int j = 0;
    for (; j + 32 <= cnt; j += 32) {
        unsigned long long pk = __ldg(&el[j + lane]);
        #pragma unroll
        for (int t = 0; t < 32; t += 4) {
            unsigned long long p0 = __shfl_sync(0xffffffffu, pk, t);
            unsigned long long p1 = __shfl_sync(0xffffffffu, pk, t + 1);
            unsigned long long p2 = __shfl_sync(0xffffffffu, pk, t + 2);
            unsigned long long p3 = __shfl_sync(0xffffffffu, pk, t + 3);
            const float* u0 = g_U + (size_t)(unsigned)p0 * G3;
            const float* u1 = g_U + (size_t)(unsigned)p1 * G3;
            const float* u2 = g_U + (size_t)(unsigned)p2 * G3;
            const float* u3 = g_U + (size_t)(unsigned)p3 * G3;
            float v00 = __ldg(u0 + lane), v01 = __ldg(u0 + lane + 32), v02 = __ldg(u0 + lane + 64);
            float v10 = __ldg(u1 + lane), v11 = __ldg(u1 + lane + 32), v12 = __ldg(u1 + lane + 64);
            float v20 = __ldg(u2 + lane), v21 = __ldg(u2 + lane + 32), v22 = __ldg(u2 + lane + 64);
            float v30 = __ldg(u3 + lane), v31 = __ldg(u3 + lane + 32), v32 = __ldg(u3 + lane + 64);
            float w0 = __uint_as_float((unsigned)(p0 >> 32));
            float w1 = __uint_as_float((unsigned)(p1 >> 32));
            float w2 = __uint_as_float((unsigned)(p2 >> 32));
            float w3 = __uint_as_float((unsigned)(p3 >> 32));
            a0 = fmaf(w0, v00, a0); a1 = fmaf(w0, v01, a1); a2 = fmaf(w0, v02, a2);
            a0 = fmaf(w1, v10, a0); a1 = fmaf(w1, v11, a1); a2 = fmaf(w1, v12, a2);
            a0 = fmaf(w2, v20, a0); a1 = fmaf(w2, v21, a1); a2 = fmaf(w2, v22, a2);
            a0 = fmaf(w3, v30, a0); a1 = fmaf(w3, v31, a1); a2 = fmaf(w3, v32, a2);
        }
    }
    int rem = cnt - j;
    if (rem > 0) {
        unsigned long long pk = (lane < rem) ? __ldg(&el[j + lane]) : 0ull;
        for (int t = 0; t < rem; t++) {
            unsigned long long p = __shfl_sync(0xffffffffu, pk, t);
            const float* ur = g_U + (size_t)(unsigned)p * G3;
            float w = __uint_as_float((unsigned)(p >> 32));
            a0 = fmaf(w, __ldg(ur + lane), a0);
            a1 = fmaf(w, __ldg(ur + lane + 32), a1);
            a2 = fmaf(w, __ldg(ur + lane + 64), a2);
        }
    }

    float dc = __ldg(&g_dinv[n]);
    a0 *= dc; a1 *= dc; a2 *= dc;

    // gates
    float h  = hprev[(size_t)n * HID + lane];
    float zp = a0 + csts[lane];
    float rp = a1 + csts[lane + 32];
    float hp = a2 + csts[lane + 64];

    const float* Wz = Ws;
    const float* Wr = Ws + HID * HID;
    const float* Wh = Ws + 2 * HID * HID;
    #pragma unroll
    for (int k = 0; k < HID; k++) {
        float hk = __shfl_sync(0xffffffffu, h, k);
        zp += hk * Wz[k * HID + lane];
        rp += hk * Wr[k * HID + lane];
    }
    float Z = 1.f / (1.f + __expf(-zp));
    float R = 1.f / (1.f + __expf(-rp));
    float hr = h * R;
    #pragma unroll
    for (int k = 0; k < HID; k++) {
        float hk = __shfl_sync(0xffffffffu, hr, k);
        hp += hk * Wh[k * HID + lane];
    }
    float Ht = tanhf(hp);
    float Hn = Z * h + (1.f - Z) * Ht;

    out[(size_t)NN + (size_t)n * HID + lane] = Hn;

    float yv = fmaxf(Hn, 0.f) * __ldg(&whead[lane]);
    #pragma unroll
    for (int off = 16; off > 0; off >>= 1)
        yv += __shfl_down_sync(0xffffffffu, yv, off);
    if (lane == 0) out[n] = yv + __ldg(bhead);
}

// ---------------------------------------------------------------------------
extern "C" void kernel_launch(void* const* d_in, const int* in_sizes, int n_in,
                              void* d_out, int out_size) {
    const float* x     = (const float*)d_in[0];
    const void*  ei    = d_in[1];
    const float* ew    = (const float*)d_in[2];
    const float* hprev = (const float*)d_in[3];
    const float* Wc[3], *bc[3], *Wl[3], *bl[3];
    for (int g = 0; g < 3; g++) {
        Wc[g] = (const float*)d_in[4 + g * 4];
        bc[g] = (const float*)d_in[5 + g * 4];
        Wl[g] = (const float*)d_in[6 + g * 4];
        bl[g] = (const float*)d_in[7 + g * 4];
    }
    const float* whead = (const float*)d_in[16];
    const float* bhead = (const float*)d_in[17];
    float* out = (float*)d_out;

    const int nscan = (NN + 1023) / 1024;   // 98

    detect_kernel<<<1, 256>>>((const int*)ei);
    prep_kernel<<<1, 128>>>(Wc[0], bc[0], Wl[0], bl[0],
                            Wc[1], bc[1], Wl[1], bl[1],
                            Wc[2], bc[2], Wl[2], bl[2]);
    init_kernel<<<(NN + 255) / 256, 256>>>();
    count_kernel<<<(NE + 255) / 256, 256>>>(ei, ew);
    scanA_kernel<<<nscan, 1024>>>();
    scanB_kernel<<<1, 128>>>(nscan);
    scanC_kernel<<<nscan, 1024>>>();
    gemm_u_kernel<<<(NN + 63) / 64, 256>>>(x);
    scatter_kernel<<<(NE + 255) / 256, 256>>>(ei, ew);
    gather_gates_kernel<<<NN / 8, 256>>>(hprev, whead, bhead, out);
}